// round 4
// baseline (speedup 1.0000x reference)
#include <cuda_runtime.h>
#include <math.h>

#define HDIM   256
#define H2DIM  512
#define SLEN   4096
#define VOCAB  8192

// ---------------- device scratch (no allocation allowed) ----------------
__device__ float g_uy[768];            // [0:256)=Uz@y+b, [256:512)=Ur@y+b, [512:768)=Uh@y+b
__device__ float g_wh[768];            // [0:256)=Wa@h+b, [256:512)=Wz@h+b, [512:768)=Wr@h+b
__device__ float g_E[SLEN];            // attention scores
__device__ float g_cipart[64 * 512];   // partial context sums
__device__ float g_z[HDIM];
__device__ float g_rh[HDIM];           // r * hidden
__device__ float g_chc[HDIM];          // Ch@Ci + Ch_b

// ---------------- helpers ----------------
__device__ __forceinline__ float warp_sum(float v) {
#pragma unroll
    for (int o = 16; o; o >>= 1) v += __shfl_xor_sync(0xffffffffu, v, o);
    return v;
}
__device__ __forceinline__ float warp_max(float v) {
#pragma unroll
    for (int o = 16; o; o >>= 1) v = fmaxf(v, __shfl_xor_sync(0xffffffffu, v, o));
    return v;
}
__device__ __forceinline__ float dot4(float4 a, float4 b) {
    return a.x * b.x + a.y * b.y + a.z * b.z + a.w * b.w;
}
// pack one float into both lanes of an f32x2 register pair
__device__ __forceinline__ unsigned long long pack2(float x) {
    unsigned long long r;
    asm("mov.b64 %0, {%1, %1};" : "=l"(r) : "f"(x));
    return r;
}
// d = a * b + d, two independent fp32 FMAs (Blackwell f32x2)
__device__ __forceinline__ void fma2(unsigned long long& d, unsigned long long a, unsigned long long b) {
    asm("fma.rn.f32x2 %0, %1, %2, %0;" : "+l"(d) : "l"(a), "l"(b));
}
__device__ __forceinline__ void unpack2(unsigned long long v, float& lo, float& hi) {
    asm("mov.b64 {%0, %1}, %2;" : "=f"(lo), "=f"(hi) : "l"(v));
}

// ================= K1: W-gemvs (Wa/Wz/Wr @ hidden + b) =================
// 24 blocks x 256 threads; warp computes 4 outputs (K=256 dots).
__global__ void __launch_bounds__(256) k_wgemv(
                        const float* __restrict__ hidden,
                        const float* __restrict__ Wa, const float* __restrict__ Wa_b,
                        const float* __restrict__ Wz, const float* __restrict__ Wz_b,
                        const float* __restrict__ Wr, const float* __restrict__ Wr_b) {
    int wid = threadIdx.x >> 5, lane = threadIdx.x & 31;
    int gw = blockIdx.x * 8 + wid;                // 0..191
    const float4* h4 = (const float4*)hidden;
    float4 hv0 = h4[lane], hv1 = h4[lane + 32];
#pragma unroll
    for (int q = 0; q < 4; q++) {
        int o = gw * 4 + q;                       // 0..767
        int mat = o >> 8, j = o & 255;
        const float* W = (mat == 0) ? Wa : (mat == 1) ? Wz : Wr;
        const float* B = (mat == 0) ? Wa_b : (mat == 1) ? Wz_b : Wr_b;
        const float4* W4 = (const float4*)(W + j * HDIM);
        float acc = dot4(W4[lane], hv0) + dot4(W4[lane + 32], hv1);
        acc = warp_sum(acc);
        if (lane == 0) g_wh[o] = acc + B[j];
    }
}

// ================= K2: fused attention GEMM + U-gemvs =================
// blocks 0..127  : attention scores E[s] = Va . tanh(Wa h + Ua enc[s] + biases)
// blocks 128..223: U{z,r,h} @ emb[tok] + b  (memory bound; overlaps attention compute)
#define KC 32
#define SA_STR 33
#define SB_STR 260
__global__ void __launch_bounds__(256) k_attn_ugemv(
                             const float* __restrict__ enc,
                             const float* __restrict__ Ua, const float* __restrict__ Ua_b,
                             const float* __restrict__ Va, const float* __restrict__ Va_b,
                             const int* __restrict__ tok, const float* __restrict__ emb,
                             const float* __restrict__ Uz, const float* __restrict__ Uz_b,
                             const float* __restrict__ Ur, const float* __restrict__ Ur_b,
                             const float* __restrict__ Uh, const float* __restrict__ Uh_b) {
    if (blockIdx.x >= 128) {
        // ---- U-gemv: warp per output row, K = 8192 ----
        int wid = threadIdx.x >> 5, lane = threadIdx.x & 31;
        int gw = (blockIdx.x - 128) * 8 + wid;    // 0..767
        int mat = gw >> 8, j = gw & 255;
        const float* W = (mat == 0) ? Uz : (mat == 1) ? Ur : Uh;
        const float* B = (mat == 0) ? Uz_b : (mat == 1) ? Ur_b : Uh_b;
        const float4* W4 = (const float4*)(W + (size_t)j * VOCAB);
        const float4* y4 = (const float4*)(emb + (size_t)tok[0] * (size_t)VOCAB);
        float acc = 0.f;
#pragma unroll 8
        for (int i = 0; i < 64; i++) {
            float4 w = W4[lane + i * 32];
            float4 y = y4[lane + i * 32];
            acc += dot4(w, y);
        }
        acc = warp_sum(acc);
        if (lane == 0) g_uy[gw] = acc + B[j];
        return;
    }

    // ---- attention tile: M=32 rows, N=256 cols, K=512 staged by KC=32 ----
    __shared__ __align__(16) float sA[KC * SA_STR];   // [kk][m], padded
    __shared__ __align__(16) float sB[KC * SB_STR];   // [kk][n], padded
    __shared__ float s_w[256];                        // Wa@h + Wa_b + Ua_b
    __shared__ float s_va[256];

    int tid = threadIdx.x;
    int tm = tid >> 5;        // warp id = m-group (4 rows)
    int tn = tid & 31;        // lane    = n-group (8 cols)
    s_w[tid] = g_wh[tid] + Ua_b[tid];
    s_va[tid] = Va[tid];

    unsigned long long acc[4][4];
#pragma unroll
    for (int a = 0; a < 4; a++)
#pragma unroll
        for (int b = 0; b < 4; b++) acc[a][b] = 0ull;

    int row0 = blockIdx.x * 32;
    const float4* enc4 = (const float4*)enc;
    const float4* Ua4 = (const float4*)Ua;

    for (int k0 = 0; k0 < H2DIM; k0 += KC) {
        __syncthreads();
        {   // stage enc tile [32 rows x 32 k] transposed -> sA[kk][m]
            int m = tid >> 3, kq = tid & 7;
            float4 v = enc4[(size_t)(row0 + m) * 128 + (k0 >> 2) + kq];
            sA[(kq * 4 + 0) * SA_STR + m] = v.x;
            sA[(kq * 4 + 1) * SA_STR + m] = v.y;
            sA[(kq * 4 + 2) * SA_STR + m] = v.z;
            sA[(kq * 4 + 3) * SA_STR + m] = v.w;
        }
#pragma unroll
        for (int t = 0; t < 8; t++) {  // stage Ua tile [256 n x 32 k] -> sB[kk][n]
            int idx = t * 256 + tid;
            int n = idx >> 3, kq = idx & 7;
            float4 v = Ua4[n * 128 + (k0 >> 2) + kq];
            sB[(kq * 4 + 0) * SB_STR + n] = v.x;
            sB[(kq * 4 + 1) * SB_STR + n] = v.y;
            sB[(kq * 4 + 2) * SB_STR + n] = v.z;
            sB[(kq * 4 + 3) * SB_STR + n] = v.w;
        }
        __syncthreads();

#pragma unroll 8
        for (int kk = 0; kk < KC; kk++) {
            unsigned long long a0 = pack2(sA[kk * SA_STR + tm * 4 + 0]);
            unsigned long long a1 = pack2(sA[kk * SA_STR + tm * 4 + 1]);
            unsigned long long a2 = pack2(sA[kk * SA_STR + tm * 4 + 2]);
            unsigned long long a3 = pack2(sA[kk * SA_STR + tm * 4 + 3]);
            const ulonglong2* bp = (const ulonglong2*)&sB[kk * SB_STR + tn * 8];
            ulonglong2 b01 = bp[0];
            ulonglong2 b23 = bp[1];
            fma2(acc[0][0], a0, b01.x); fma2(acc[0][1], a0, b01.y);
            fma2(acc[0][2], a0, b23.x); fma2(acc[0][3], a0, b23.y);
            fma2(acc[1][0], a1, b01.x); fma2(acc[1][1], a1, b01.y);
            fma2(acc[1][2], a1, b23.x); fma2(acc[1][3], a1, b23.y);
            fma2(acc[2][0], a2, b01.x); fma2(acc[2][1], a2, b01.y);
            fma2(acc[2][2], a2, b23.x); fma2(acc[2][3], a2, b23.y);
            fma2(acc[3][0], a3, b01.x); fma2(acc[3][1], a3, b01.y);
            fma2(acc[3][2], a3, b23.x); fma2(acc[3][3], a3, b23.y);
        }
    }

    // epilogue: E[row] = sum_n Va[n] * tanh(acc + s_w[n]) + Va_b
    float vb = Va_b[0];
#pragma unroll
    for (int mi = 0; mi < 4; mi++) {
        float s = 0.f;
#pragma unroll
        for (int p = 0; p < 4; p++) {
            float lo, hi;
            unpack2(acc[mi][p], lo, hi);
            int n = tn * 8 + p * 2;
            s += s_va[n] * tanhf(lo + s_w[n]);
            s += s_va[n + 1] * tanhf(hi + s_w[n + 1]);
        }
        s = warp_sum(s);
        if (tn == 0) g_E[row0 + tm * 4 + mi] = s + vb;
    }
}

// ================= K3: softmax over scores -> aij (writes d_out aij region) =================
__global__ void __launch_bounds__(1024) k_softmax(float* __restrict__ aij) {   // 1 block, 1024 threads
    __shared__ float sred[32];
    __shared__ float sM, sS;
    int tid = threadIdx.x, wid = tid >> 5, lane = tid & 31;
    const float4* E4 = (const float4*)g_E;
    float4 v = E4[tid];
    float m = fmaxf(fmaxf(v.x, v.y), fmaxf(v.z, v.w));
    m = warp_max(m);
    if (lane == 0) sred[wid] = m;
    __syncthreads();
    if (wid == 0) {
        float t = warp_max(sred[lane]);
        if (lane == 0) sM = t;
    }
    __syncthreads();
    float M = sM;
    float e0 = expf(v.x - M), e1 = expf(v.y - M), e2 = expf(v.z - M), e3 = expf(v.w - M);
    float s = warp_sum(e0 + e1 + e2 + e3);
    if (lane == 0) sred[wid] = s;
    __syncthreads();
    if (wid == 0) {
        float t = warp_sum(sred[lane]);
        if (lane == 0) sS = t;
    }
    __syncthreads();
    float inv = 1.f / sS;
    float4* A4 = (float4*)aij;
    A4[tid] = make_float4(e0 * inv, e1 * inv, e2 * inv, e3 * inv);
}

// ================= K4: context partials Ci = sum_s aij[s] * enc[s,:] =================
__global__ void __launch_bounds__(256) k_ci(const float* __restrict__ enc, const float* __restrict__ aij) {
    __shared__ float sa[64];
    int tid = threadIdx.x;
    int s0 = blockIdx.x * 64;
    if (tid < 64) sa[tid] = aij[s0 + tid];
    __syncthreads();
    float a0 = 0.f, a1 = 0.f;
#pragma unroll 4
    for (int s = 0; s < 64; s++) {
        const float* r = enc + (size_t)(s0 + s) * H2DIM;
        float a = sa[s];
        a0 += a * r[tid];
        a1 += a * r[tid + 256];
    }
    g_cipart[blockIdx.x * 512 + tid] = a0;
    g_cipart[blockIdx.x * 512 + tid + 256] = a1;
}

// ================= K5: C-gemvs + z, r*h, Ch@Ci =================
// 24 blocks x 256 threads; blocks [0..8)=Cz, [8..16)=Cr, [16..24)=Ch
__global__ void __launch_bounds__(256) k_cgemv(
                        const float* __restrict__ hidden,
                        const float* __restrict__ Cz, const float* __restrict__ Cz_b,
                        const float* __restrict__ Cr, const float* __restrict__ Cr_b,
                        const float* __restrict__ Ch, const float* __restrict__ Ch_b) {
    __shared__ __align__(16) float sCi[H2DIM];
    int tid = threadIdx.x;
    float c0 = 0.f, c1 = 0.f;
#pragma unroll 8
    for (int p = 0; p < 64; p++) {
        c0 += g_cipart[p * 512 + tid];
        c1 += g_cipart[p * 512 + tid + 256];
    }
    sCi[tid] = c0;
    sCi[tid + 256] = c1;
    __syncthreads();

    int mat = blockIdx.x >> 3;
    int jb = (blockIdx.x & 7) * 32;
    const float* C = (mat == 0) ? Cz : (mat == 1) ? Cr : Ch;
    const float* B = (mat == 0) ? Cz_b : (mat == 1) ? Cr_b : Ch_b;
    int wid = tid >> 5, lane = tid & 31;
    const float4* Ci4 = (const float4*)sCi;
    float4 ci0 = Ci4[lane], ci1 = Ci4[lane + 32], ci2 = Ci4[lane + 64], ci3 = Ci4[lane + 96];
#pragma unroll
    for (int q = 0; q < 4; q++) {
        int j = jb + wid * 4 + q;
        const float4* C4 = (const float4*)(C + j * H2DIM);
        float acc = dot4(C4[lane], ci0) + dot4(C4[lane + 32], ci1)
                  + dot4(C4[lane + 64], ci2) + dot4(C4[lane + 96], ci3);
        acc = warp_sum(acc);
        if (lane == 0) {
            if (mat == 0) {
                float v = g_uy[j] + g_wh[256 + j] + acc + B[j];
                g_z[j] = 1.f / (1.f + expf(-v));
            } else if (mat == 1) {
                float v = g_uy[256 + j] + g_wh[512 + j] + acc + B[j];
                float r = 1.f / (1.f + expf(-v));
                g_rh[j] = r * hidden[j];
            } else {
                g_chc[j] = acc + B[j];
            }
        }
    }
}

// ================= K6: Wh@(r*h), candidate c, hidden_new =================
__global__ void __launch_bounds__(256) k_hnew(
                       const float* __restrict__ hidden,
                       const float* __restrict__ Wh, const float* __restrict__ Wh_b,
                       float* __restrict__ out) {   // 8 blocks x 256 threads
    __shared__ __align__(16) float srh[HDIM];
    int tid = threadIdx.x;
    srh[tid] = g_rh[tid];
    __syncthreads();
    int wid = tid >> 5, lane = tid & 31;
    const float4* R4 = (const float4*)srh;
    float4 r0 = R4[lane], r1 = R4[lane + 32];
#pragma unroll
    for (int q = 0; q < 4; q++) {
        int j = blockIdx.x * 32 + wid * 4 + q;
        const float4* W4 = (const float4*)(Wh + j * HDIM);
        float acc = dot4(W4[lane], r0) + dot4(W4[lane + 32], r1);
        acc = warp_sum(acc);
        if (lane == 0) {
            float c = tanhf(g_uy[512 + j] + acc + Wh_b[j] + g_chc[j]);
            float z = g_z[j];
            out[VOCAB + j] = (1.f - z) * c + z * hidden[j];
        }
    }
}

// ================= K7: logits = V_w @ hidden_new + V_b =================
__global__ void __launch_bounds__(256) k_logits(
                         const float* __restrict__ Vw, const float* __restrict__ Vb,
                         float* __restrict__ out) {  // 256 blocks x 256 threads
    __shared__ __align__(16) float sh[HDIM];
    int tid = threadIdx.x;
    sh[tid] = out[VOCAB + tid];   // hidden_new
    __syncthreads();
    int wid = tid >> 5, lane = tid & 31;
    const float4* Hn4 = (const float4*)sh;
    float4 h0 = Hn4[lane], h1 = Hn4[lane + 32];
#pragma unroll
    for (int q = 0; q < 4; q++) {
        int j = blockIdx.x * 32 + wid * 4 + q;
        const float4* W4 = (const float4*)(Vw + j * HDIM);
        float acc = dot4(W4[lane], h0) + dot4(W4[lane + 32], h1);
        acc = warp_sum(acc);
        if (lane == 0) out[j] = acc + Vb[j];
    }
}

// ================= K8: in-place log_softmax over 8192 logits =================
__global__ void __launch_bounds__(1024) k_logsoftmax(float* __restrict__ out) {  // 1 block, 1024 threads
    __shared__ float sred[32];
    __shared__ float sM, sS;
    int tid = threadIdx.x, wid = tid >> 5, lane = tid & 31;
    float4* O4 = (float4*)out;
    float4 v0 = O4[tid * 2], v1 = O4[tid * 2 + 1];
    float m = fmaxf(fmaxf(fmaxf(v0.x, v0.y), fmaxf(v0.z, v0.w)),
                    fmaxf(fmaxf(v1.x, v1.y), fmaxf(v1.z, v1.w)));
    m = warp_max(m);
    if (lane == 0) sred[wid] = m;
    __syncthreads();
    if (wid == 0) {
        float t = warp_max(sred[lane]);
        if (lane == 0) sM = t;
    }
    __syncthreads();
    float M = sM;
    float s = expf(v0.x - M) + expf(v0.y - M) + expf(v0.z - M) + expf(v0.w - M)
            + expf(v1.x - M) + expf(v1.y - M) + expf(v1.z - M) + expf(v1.w - M);
    s = warp_sum(s);
    if (lane == 0) sred[wid] = s;
    __syncthreads();
    if (wid == 0) {
        float t = warp_sum(sred[lane]);
        if (lane == 0) sS = t;
    }
    __syncthreads();
    float off = M + logf(sS);
    v0.x -= off; v0.y -= off; v0.z -= off; v0.w -= off;
    v1.x -= off; v1.y -= off; v1.z -= off; v1.w -= off;
    O4[tid * 2] = v0;
    O4[tid * 2 + 1] = v1;
}

// ================= launch =================
extern "C" void kernel_launch(void* const* d_in, const int* in_sizes, int n_in,
                              void* d_out, int out_size) {
    (void)in_sizes; (void)n_in; (void)out_size;
    const int*   tok    = (const int*)  d_in[0];
    const float* hidden = (const float*)d_in[1];
    const float* enc    = (const float*)d_in[2];
    const float* emb    = (const float*)d_in[3];
    const float* Uz_w = (const float*)d_in[4],  *Uz_b = (const float*)d_in[5];
    const float* Wz_w = (const float*)d_in[6],  *Wz_b = (const float*)d_in[7];
    const float* Cz_w = (const float*)d_in[8],  *Cz_b = (const float*)d_in[9];
    const float* Ur_w = (const float*)d_in[10], *Ur_b = (const float*)d_in[11];
    const float* Wr_w = (const float*)d_in[12], *Wr_b = (const float*)d_in[13];
    const float* Cr_w = (const float*)d_in[14], *Cr_b = (const float*)d_in[15];
    const float* Uh_w = (const float*)d_in[16], *Uh_b = (const float*)d_in[17];
    const float* Wh_w = (const float*)d_in[18], *Wh_b = (const float*)d_in[19];
    const float* Ch_w = (const float*)d_in[20], *Ch_b = (const float*)d_in[21];
    const float* Ua_w = (const float*)d_in[22], *Ua_b = (const float*)d_in[23];
    const float* Wa_w = (const float*)d_in[24], *Wa_b = (const float*)d_in[25];
    const float* Va_w = (const float*)d_in[26], *Va_b = (const float*)d_in[27];
    const float* V_w  = (const float*)d_in[28], *V_b  = (const float*)d_in[29];
    float* out = (float*)d_out;  // layout: [0:8192)=log_softmax, [8192:8448)=hidden_new, [8448:12544)=aij

    k_wgemv<<<24, 256>>>(hidden, Wa_w, Wa_b, Wz_w, Wz_b, Wr_w, Wr_b);
    k_attn_ugemv<<<224, 256>>>(enc, Ua_w, Ua_b, Va_w, Va_b, tok, emb,
                               Uz_w, Uz_b, Ur_w, Ur_b, Uh_w, Uh_b);
    k_softmax<<<1, 1024>>>(out + VOCAB + HDIM);
    k_ci<<<64, 256>>>(enc, out + VOCAB + HDIM);
    k_cgemv<<<24, 256>>>(hidden, Cz_w, Cz_b, Cr_w, Cr_b, Ch_w, Ch_b);
    k_hnew<<<8, 256>>>(hidden, Wh_w, Wh_b, out);
    k_logits<<<256, 256>>>(V_w, V_b, out);
    k_logsoftmax<<<1, 1024>>>(out);
}